// round 14
// baseline (speedup 1.0000x reference)
#include <cuda_runtime.h>
#include <math.h>

#define NB 64
#define NT 2048
#define ND 64
#define NTM 2047
#define NG 4
#define NGD 16

// ---------------- device scratch (no allocations allowed) ----------------
__device__ float g_S[NG * NGD * 64];                    // skew matrices, 16 KB
__device__ float g_fp[(size_t)NB * NTM * 64];           // projected features, 33.5 MB
__device__ float g_h[(size_t)NB * NT * ND];             // h = x + interp(f), 33.5 MB
__device__ float g_part[16 * NB * ND];                  // pooled partial sums (deterministic)
__device__ float g_sgate[NB * ND];                      // SE gate

// ---------------- K1: build S = tril(W,-1) - tril(W,-1)^T ----------------
__global__ void k_prep(const float* __restrict__ W) {
    int i = blockIdx.x * blockDim.x + threadIdx.x;
    if (i < NG * NGD * 64) {
        int j = i & 7;
        int r = (i >> 3) & 7;
        int gd = i >> 6;
        float v = 0.f;
        if (r > j)      v =  W[gd * 64 + r * 8 + j];
        else if (r < j) v = -W[gd * 64 + j * 8 + r];
        g_S[i] = v;
    }
}

__device__ __forceinline__ void fma8(float* acc, float s, float4 r0, float4 r1) {
    acc[0] = fmaf(s, r0.x, acc[0]);
    acc[1] = fmaf(s, r0.y, acc[1]);
    acc[2] = fmaf(s, r0.z, acc[2]);
    acc[3] = fmaf(s, r0.w, acc[3]);
    acc[4] = fmaf(s, r1.x, acc[4]);
    acc[5] = fmaf(s, r1.y, acc[5]);
    acc[6] = fmaf(s, r1.z, acc[6]);
    acc[7] = fmaf(s, r1.w, acc[7]);
}

// ---------------- K2: expm + LN + projection, fused --------------------
// 8 threads per 8x8 matrix (one row each). One warp = one (b,t): lanes
// [8g, 8g+8) handle group g. Projection partials reduced across groups
// with shfl_xor(8)/shfl_xor(16).
__global__ void __launch_bounds__(256) k_main(
    const float* __restrict__ x, const float* __restrict__ mask,
    const float* __restrict__ lng, const float* __restrict__ lnb,
    const float* __restrict__ pw, const float* __restrict__ pb) {
    // 32 matrix slots, stride 68 floats -> bank offset 4*slot, conflict-free
    __shared__ float As[32 * 68];

    const int lane = threadIdx.x & 31;
    const int warp = threadIdx.x >> 5;
    const int g = lane >> 3;
    const int r = lane & 7;
    float* Asl = As + (warp * 4 + g) * 68;

    const int bt = blockIdx.x * 8 + warp;          // (b,t) pair, t in [0, 2046]
    const int b = bt / NTM;
    const int t = bt - b * NTM;
    const float mk = mask[b * NT + t + 1];

    const float* xp = x + (size_t)(b * NT + t) * ND + g * NGD;
    float4 a0 = *(const float4*)(xp + 0);
    float4 a1 = *(const float4*)(xp + 4);
    float4 a2 = *(const float4*)(xp + 8);
    float4 a3 = *(const float4*)(xp + 12);
    float4 c0 = *(const float4*)(xp + ND + 0);
    float4 c1 = *(const float4*)(xp + ND + 4);
    float4 c2 = *(const float4*)(xp + ND + 8);
    float4 c3 = *(const float4*)(xp + ND + 12);

    float dx[16];
    dx[0]  = (c0.x - a0.x) * mk;  dx[1]  = (c0.y - a0.y) * mk;
    dx[2]  = (c0.z - a0.z) * mk;  dx[3]  = (c0.w - a0.w) * mk;
    dx[4]  = (c1.x - a1.x) * mk;  dx[5]  = (c1.y - a1.y) * mk;
    dx[6]  = (c1.z - a1.z) * mk;  dx[7]  = (c1.w - a1.w) * mk;
    dx[8]  = (c2.x - a2.x) * mk;  dx[9]  = (c2.y - a2.y) * mk;
    dx[10] = (c2.z - a2.z) * mk;  dx[11] = (c2.w - a2.w) * mk;
    dx[12] = (c3.x - a3.x) * mk;  dx[13] = (c3.y - a3.y) * mk;
    dx[14] = (c3.z - a3.z) * mk;  dx[15] = (c3.w - a3.w) * mk;

    // M row r = sum_d dx[d] * S[g,d,r,:], then scale by 2^-6
    float a[8];
#pragma unroll
    for (int j = 0; j < 8; j++) a[j] = 0.f;
    const float* Sp = g_S + g * (NGD * 64) + r * 8;
#pragma unroll
    for (int d = 0; d < 16; d++) {
        float4 s0 = *(const float4*)(Sp + d * 64);
        float4 s1 = *(const float4*)(Sp + d * 64 + 4);
        fma8(a, dx[d], s0, s1);
    }
#pragma unroll
    for (int j = 0; j < 8; j++) a[j] *= (1.f / 64.f);

    *(float4*)(Asl + r * 8)     = make_float4(a[0], a[1], a[2], a[3]);
    *(float4*)(Asl + r * 8 + 4) = make_float4(a[4], a[5], a[6], a[7]);
    __syncwarp();

    // Taylor-6 of exp(A)  (truncation err ~2e-9, ref uses 12)
    float term[8], out[8];
#pragma unroll
    for (int j = 0; j < 8; j++) { float v = (j == r) ? 1.f : 0.f; term[j] = v; out[j] = v; }
#pragma unroll
    for (int k = 1; k <= 6; k++) {
        float acc[8];
#pragma unroll
        for (int j = 0; j < 8; j++) acc[j] = 0.f;
#pragma unroll
        for (int kk = 0; kk < 8; kk++) {
            float4 r0 = *(const float4*)(Asl + kk * 8);
            float4 r1 = *(const float4*)(Asl + kk * 8 + 4);
            fma8(acc, term[kk], r0, r1);
        }
        const float invk = 1.f / (float)k;
#pragma unroll
        for (int j = 0; j < 8; j++) { term[j] = acc[j] * invk; out[j] += term[j]; }
    }

    // 6 squarings: out = out @ out
#pragma unroll 1
    for (int sq = 0; sq < 6; sq++) {
        __syncwarp();
        *(float4*)(Asl + r * 8)     = make_float4(out[0], out[1], out[2], out[3]);
        *(float4*)(Asl + r * 8 + 4) = make_float4(out[4], out[5], out[6], out[7]);
        __syncwarp();
        float acc[8];
#pragma unroll
        for (int j = 0; j < 8; j++) acc[j] = 0.f;
#pragma unroll
        for (int kk = 0; kk < 8; kk++) {
            float4 r0 = *(const float4*)(Asl + kk * 8);
            float4 r1 = *(const float4*)(Asl + kk * 8 + 4);
            fma8(acc, out[kk], r0, r1);
        }
#pragma unroll
        for (int j = 0; j < 8; j++) out[j] = acc[j];
    }

    // LayerNorm over the 64 matrix entries (reduce across the 8-lane group)
    float sum = 0.f, sqs = 0.f;
#pragma unroll
    for (int j = 0; j < 8; j++) { sum += out[j]; sqs = fmaf(out[j], out[j], sqs); }
#pragma unroll
    for (int off = 1; off < 8; off <<= 1) {
        sum += __shfl_xor_sync(0xffffffffu, sum, off);
        sqs += __shfl_xor_sync(0xffffffffu, sqs, off);
    }
    float mean = sum * (1.f / 64.f);
    float var  = sqs * (1.f / 64.f) - mean * mean;
    float rstd = rsqrtf(var + 1e-5f);

    float4 lg0 = *(const float4*)(lng + r * 8);
    float4 lg1 = *(const float4*)(lng + r * 8 + 4);
    float4 lb0 = *(const float4*)(lnb + r * 8);
    float4 lb1 = *(const float4*)(lnb + r * 8 + 4);
    float fn[8];
    fn[0] = (out[0] - mean) * rstd * lg0.x + lb0.x;
    fn[1] = (out[1] - mean) * rstd * lg0.y + lb0.y;
    fn[2] = (out[2] - mean) * rstd * lg0.z + lb0.z;
    fn[3] = (out[3] - mean) * rstd * lg0.w + lb0.w;
    fn[4] = (out[4] - mean) * rstd * lg1.x + lb1.x;
    fn[5] = (out[5] - mean) * rstd * lg1.y + lb1.y;
    fn[6] = (out[6] - mean) * rstd * lg1.z + lb1.z;
    fn[7] = (out[7] - mean) * rstd * lg1.w + lb1.w;

    // stage normalized features, then fused projection f(256) @ P(256,64)
    __syncwarp();
    *(float4*)(Asl + r * 8)     = make_float4(fn[0], fn[1], fn[2], fn[3]);
    *(float4*)(Asl + r * 8 + 4) = make_float4(fn[4], fn[5], fn[6], fn[7]);
    __syncwarp();

    float acc[8];
#pragma unroll
    for (int j = 0; j < 8; j++) acc[j] = 0.f;
    const float* pwp = pw + (g * 64) * 64 + r * 8;   // row (g*64+c), cols [r*8, r*8+8)
#pragma unroll 4
    for (int c = 0; c < 64; c++) {
        float fv = Asl[c];                            // group broadcast
        float4 p0 = *(const float4*)(pwp + c * 64);
        float4 p1 = *(const float4*)(pwp + c * 64 + 4);
        fma8(acc, fv, p0, p1);
    }
    // sum partials over the 4 groups
#pragma unroll
    for (int j = 0; j < 8; j++) {
        acc[j] += __shfl_xor_sync(0xffffffffu, acc[j], 8);
        acc[j] += __shfl_xor_sync(0xffffffffu, acc[j], 16);
    }
    if (g == 0) {
        float4 pb0 = *(const float4*)(pb + r * 8);
        float4 pb1 = *(const float4*)(pb + r * 8 + 4);
        float* op = g_fp + (size_t)bt * 64 + r * 8;
        *(float4*)(op)     = make_float4(acc[0] + pb0.x, acc[1] + pb0.y, acc[2] + pb0.z, acc[3] + pb0.w);
        *(float4*)(op + 4) = make_float4(acc[4] + pb1.x, acc[5] + pb1.y, acc[6] + pb1.z, acc[7] + pb1.w);
    }
}

// ---------------- K3: h = x + lin_interp(f), masked pooled partials -----
__global__ void __launch_bounds__(256) k_interp(
    const float* __restrict__ x, const float* __restrict__ mask) {
    const int b  = blockIdx.y;
    const int d  = threadIdx.x & 63;
    const int tq = threadIdx.x >> 6;
    const float sc = (float)(2047.0 / 2048.0);
    float acc = 0.f;
    const int t0 = blockIdx.x * 128;
#pragma unroll 4
    for (int i = 0; i < 32; i++) {
        int t = t0 + i * 4 + tq;
        float pos = ((float)t + 0.5f) * sc - 0.5f;
        pos = fminf(fmaxf(pos, 0.f), 2046.0f);
        float fl = floorf(pos);
        int i0 = (int)fl;
        int i1 = min(i0 + 1, 2046);
        float w = pos - fl;
        float f0 = g_fp[((size_t)b * NTM + i0) * 64 + d];
        float f1 = g_fp[((size_t)b * NTM + i1) * 64 + d];
        size_t xi = ((size_t)b * NT + t) * 64 + d;
        float hv = x[xi] + f0 * (1.f - w) + f1 * w;
        g_h[xi] = hv;
        acc += hv * mask[b * NT + t];
    }
    __shared__ float red[256];
    red[threadIdx.x] = acc;
    __syncthreads();
    if (tq == 0) {
        float s = red[d] + red[d + 64] + red[d + 128] + red[d + 192];
        g_part[blockIdx.x * (NB * ND) + b * ND + d] = s;   // deterministic partials
    }
}

// ---------------- K4: SE gate (tiny) + copy mask into output tail -------
__global__ void k_se(const float* __restrict__ mask,
                     const float* __restrict__ w1, const float* __restrict__ b1,
                     const float* __restrict__ w2, const float* __restrict__ b2,
                     float* __restrict__ outp, long long out_size) {
    const int b = blockIdx.x;        // 64 blocks x 64 threads
    const int tid = threadIdx.x;
    __shared__ float sm[64];
    __shared__ float hid[4];
    __shared__ float dsh;

    float ds = 0.f;
    for (int t = tid; t < NT; t += 64) ds += mask[b * NT + t];
    sm[tid] = ds;
    __syncthreads();
    if (tid == 0) {
        float s = 0.f;
        for (int i = 0; i < 64; i++) s += sm[i];
        dsh = s;
    }
    __syncthreads();
    const float denom = dsh;

    float p = 0.f;
#pragma unroll
    for (int c = 0; c < 16; c++) p += g_part[c * (NB * ND) + b * ND + tid];
    p /= denom;
    __syncthreads();
    sm[tid] = p;
    __syncthreads();
    if (tid < 4) {
        float acc = b1[tid];
        for (int dd = 0; dd < 64; dd++) acc += sm[dd] * w1[dd * 4 + tid];
        hid[tid] = 0.5f * acc * (1.f + erff(acc * 0.70710678118654752f)); // exact GELU
    }
    __syncthreads();
    float o = b2[tid];
#pragma unroll
    for (int j = 0; j < 4; j++) o += hid[j] * w2[j * 64 + tid];
    g_sgate[b * ND + tid] = 1.f / (1.f + expf(-o));

    // mask passthrough (second tuple element), if the output buffer holds it
    const size_t base = (size_t)NB * NT * ND;
    for (int t = tid; t < NT; t += 64) {
        size_t idx = base + (size_t)b * NT + t;
        if ((long long)idx < out_size) outp[idx] = mask[b * NT + t];
    }
}

// ---------------- K5: out = h * s + x ------------------------------------
__global__ void __launch_bounds__(256) k_final(
    const float* __restrict__ x, float* __restrict__ out) {
    const int i = blockIdx.x * 256 + threadIdx.x;    // < NB*NT*ND = 2^23
    const int d = i & 63;
    const int b = i >> 17;                           // NT*ND = 2^17
    const float s = g_sgate[b * ND + d];
    out[i] = g_h[i] * s + x[i];
}

// ---------------- launch ---------------------------------------------------
extern "C" void kernel_launch(void* const* d_in, const int* in_sizes, int n_in,
                              void* d_out, int out_size) {
    const float* x     = (const float*)d_in[0];
    const float* mask  = (const float*)d_in[1];
    const float* W     = (const float*)d_in[2];
    const float* lng   = (const float*)d_in[3];
    const float* lnb   = (const float*)d_in[4];
    const float* pw    = (const float*)d_in[5];
    const float* pb    = (const float*)d_in[6];
    const float* w1    = (const float*)d_in[7];
    const float* b1    = (const float*)d_in[8];
    const float* w2    = (const float*)d_in[9];
    const float* b2    = (const float*)d_in[10];
    float* out = (float*)d_out;

    k_prep<<<16, 256>>>(W);
    k_main<<<(NB * NTM) / 8, 256>>>(x, mask, lng, lnb, pw, pb);   // 16376 blocks
    dim3 gi(16, NB);
    k_interp<<<gi, 256>>>(x, mask);
    k_se<<<NB, 64>>>(mask, w1, b1, w2, b2, out, (long long)out_size);
    k_final<<<(NB * NT * ND) / 256, 256>>>(x, out);               // 32768 blocks
}

// round 15
// speedup vs baseline: 2.7591x; 2.7591x over previous
#include <cuda_runtime.h>
#include <math.h>

#define NB 64
#define NT 2048
#define ND 64
#define NTM 2047

typedef unsigned long long u64;

// ---------------- device scratch ----------------
__device__ float g_S[4 * 16 * 64];            // skew, transposed: [g][d][j][i] = S[i][j]
__device__ float g_lngT[64];                  // gamma transposed: [j*8+i] = gamma[i*8+j]
__device__ float g_lnbT[64];
__device__ float g_fp[(size_t)NB * NTM * 64]; // projected features
__device__ float g_part[16 * NB * ND];        // pooled partials (deterministic)
__device__ float g_sgate[NB * ND];

// ---------------- f32x2 packed helpers ----------------
__device__ __forceinline__ u64 f2fma(u64 a, u64 b, u64 c) {
    u64 d; asm("fma.rn.f32x2 %0,%1,%2,%3;" : "=l"(d) : "l"(a), "l"(b), "l"(c)); return d;
}
__device__ __forceinline__ u64 f2mul(u64 a, u64 b) {
    u64 d; asm("mul.rn.f32x2 %0,%1,%2;" : "=l"(d) : "l"(a), "l"(b)); return d;
}
__device__ __forceinline__ u64 f2add(u64 a, u64 b) {
    u64 d; asm("add.rn.f32x2 %0,%1,%2;" : "=l"(d) : "l"(a), "l"(b)); return d;
}
__device__ __forceinline__ u64 fdup(float x) {
    u64 d; asm("mov.b64 %0,{%1,%1};" : "=l"(d) : "f"(x)); return d;
}
__device__ __forceinline__ void funp(u64 v, float& lo, float& hi) {
    asm("mov.b64 {%0,%1},%2;" : "=f"(lo), "=f"(hi) : "l"(v));
}
// column j of identity, packed pair ip
__device__ __forceinline__ u64 icol(int j, int ip) {
    if (ip != (j >> 1)) return 0ULL;
    return (j & 1) ? (0x3F800000ULL << 32) : 0x3F800000ULL;
}

// ---------------- K1: prep transposed S + LN tables ----------------
__global__ void k_prep(const float* __restrict__ W,
                       const float* __restrict__ lng, const float* __restrict__ lnb) {
    int i = blockIdx.x * 256 + threadIdx.x;
    if (i < 4096) {
        int ir = i & 7;          // row of S
        int j  = (i >> 3) & 7;   // col of S
        int gd = i >> 6;
        float v = 0.f;
        if (ir > j)      v =  W[gd * 64 + ir * 8 + j];
        else if (ir < j) v = -W[gd * 64 + j * 8 + ir];
        g_S[i] = v;              // layout [gd][j][ir]
    } else if (i < 4160) {
        int o = i - 4096;
        int j = o >> 3, ir = o & 7;
        g_lngT[o] = lng[ir * 8 + j];
        g_lnbT[o] = lnb[ir * 8 + j];
    }
}

// ---------------- in-register 8x8 matmul (column-major packed pairs) ------
__device__ __forceinline__ void dup_col(const u64* M, int j, u64* t) {
#pragma unroll
    for (int q = 0; q < 4; q++) {
        float lo, hi; funp(M[j * 4 + q], lo, hi);
        t[2 * q] = fdup(lo); t[2 * q + 1] = fdup(hi);
    }
}
// D = C * C  (D distinct from C)
__device__ __forceinline__ void mm_sq(u64* D, const u64* C) {
#pragma unroll
    for (int j = 0; j < 8; j++) {
        u64 tt[8]; dup_col(C, j, tt);
#pragma unroll
        for (int ip = 0; ip < 4; ip++) {
            u64 acc = f2mul(tt[0], C[ip]);
#pragma unroll
            for (int kk = 1; kk < 8; kk++) acc = f2fma(tt[kk], C[kk * 4 + ip], acc);
            D[j * 4 + ip] = acc;
        }
    }
}
// C = I + (A*C) * invk   (in place, column-wise safe)
__device__ __forceinline__ void horner(u64* C, const u64* A, float invk) {
    u64 ik = fdup(invk);
#pragma unroll
    for (int j = 0; j < 8; j++) {
        u64 tt[8]; dup_col(C, j, tt);
        u64 nc[4];
#pragma unroll
        for (int ip = 0; ip < 4; ip++) {
            u64 acc = f2mul(tt[0], A[ip]);
#pragma unroll
            for (int kk = 1; kk < 8; kk++) acc = f2fma(tt[kk], A[kk * 4 + ip], acc);
            nc[ip] = acc;
        }
#pragma unroll
        for (int ip = 0; ip < 4; ip++) C[j * 4 + ip] = f2fma(nc[ip], ik, icol(j, ip));
    }
}

// ---------------- K2: Lie-proj + expm + LN + projection, 1 thread/matrix --
// block = 128 threads = 32 (b,t) x 4 groups. smem: pw 64KB | fn 32KB | S 16.5KB
__global__ void __launch_bounds__(128, 2) k_main(
    const float* __restrict__ x, const float* __restrict__ mask,
    const float* __restrict__ pw, const float* __restrict__ pb) {
    extern __shared__ float sm[];
    float* s_pw = sm;              // 16384 floats
    float* s_fn = sm + 16384;      // 8192 floats, row = feature c, 32 cols
    float* s_S  = sm + 24576;      // 4*1032 floats (padded for bank spread)
    const int tid = threadIdx.x;

    {   // stage pw and S
        const float4* src = (const float4*)pw;
        float4* dst = (float4*)s_pw;
#pragma unroll
        for (int i = 0; i < 32; i++) dst[tid + i * 128] = src[tid + i * 128];
#pragma unroll
        for (int k = 0; k < 32; k++) {
            int i = tid + k * 128;
            s_S[(i >> 10) * 1032 + (i & 1023)] = g_S[i];
        }
    }
    __syncthreads();

    // ---- phase 1: M = (1/16) * sum_d dx_d * S[g,d]  (column-major pairs) --
    const int p = tid >> 2, g = tid & 3;
    const int bt = blockIdx.x * 32 + p;       // 64*2047 = 131008 = 4094*32 exact
    const int b = bt / NTM;
    const int t = bt - b * NTM;
    const float mk = mask[b * NT + t + 1];
    const float sc = mk * 0.0625f;

    const float* xp = x + ((size_t)(b * NT + t)) * ND + g * 16;
    ulonglong2 xa0 = *(const ulonglong2*)(xp);
    ulonglong2 xa1 = *(const ulonglong2*)(xp + 4);
    ulonglong2 xa2 = *(const ulonglong2*)(xp + 8);
    ulonglong2 xa3 = *(const ulonglong2*)(xp + 12);
    ulonglong2 xc0 = *(const ulonglong2*)(xp + ND);
    ulonglong2 xc1 = *(const ulonglong2*)(xp + ND + 4);
    ulonglong2 xc2 = *(const ulonglong2*)(xp + ND + 8);
    ulonglong2 xc3 = *(const ulonglong2*)(xp + ND + 12);

    const u64 NEG1 = fdup(-1.f);
    u64 dxp[8];
    dxp[0] = f2fma(xa0.x, NEG1, xc0.x); dxp[1] = f2fma(xa0.y, NEG1, xc0.y);
    dxp[2] = f2fma(xa1.x, NEG1, xc1.x); dxp[3] = f2fma(xa1.y, NEG1, xc1.y);
    dxp[4] = f2fma(xa2.x, NEG1, xc2.x); dxp[5] = f2fma(xa2.y, NEG1, xc2.y);
    dxp[6] = f2fma(xa3.x, NEG1, xc3.x); dxp[7] = f2fma(xa3.y, NEG1, xc3.y);

    u64 dxd[16];
#pragma unroll
    for (int q = 0; q < 8; q++) {
        float lo, hi; funp(dxp[q], lo, hi);
        dxd[2 * q]     = fdup(lo * sc);
        dxd[2 * q + 1] = fdup(hi * sc);
    }

    u64 m2[32];
#pragma unroll
    for (int i = 0; i < 32; i++) m2[i] = 0ULL;
    const float* sp = s_S + g * 1032;
#pragma unroll
    for (int d = 0; d < 16; d++) {
#pragma unroll
        for (int j = 0; j < 8; j++) {
            ulonglong2 v0 = *(const ulonglong2*)(sp + d * 64 + j * 8);
            ulonglong2 v1 = *(const ulonglong2*)(sp + d * 64 + j * 8 + 4);
            m2[j * 4 + 0] = f2fma(dxd[d], v0.x, m2[j * 4 + 0]);
            m2[j * 4 + 1] = f2fma(dxd[d], v0.y, m2[j * 4 + 1]);
            m2[j * 4 + 2] = f2fma(dxd[d], v1.x, m2[j * 4 + 2]);
            m2[j * 4 + 3] = f2fma(dxd[d], v1.y, m2[j * 4 + 3]);
        }
    }

    // ---- phase 2: exp(M/16)^16 = (Taylor-6 Horner)^(2^4), then LayerNorm --
    u64 c2[32];
    {
        u64 i6 = fdup(1.f / 6.f);
#pragma unroll
        for (int j = 0; j < 8; j++)
#pragma unroll
            for (int ip = 0; ip < 4; ip++)
                c2[j * 4 + ip] = f2fma(m2[j * 4 + ip], i6, icol(j, ip));
    }
    horner(c2, m2, 0.2f);
    horner(c2, m2, 0.25f);
    horner(c2, m2, 1.f / 3.f);
    horner(c2, m2, 0.5f);
    horner(c2, m2, 1.f);
    {
        u64 d2[32];
        mm_sq(d2, c2);
        mm_sq(c2, d2);
        mm_sq(d2, c2);
        mm_sq(c2, d2);
    }

    // LayerNorm over own 64 entries — fully thread-local
    float sum, sqs;
    {
        u64 s0 = c2[0], s1 = c2[1], s2v = c2[2], s3 = c2[3];
        u64 q0 = f2mul(c2[0], c2[0]), q1 = f2mul(c2[1], c2[1]);
        u64 q2 = f2mul(c2[2], c2[2]), q3 = f2mul(c2[3], c2[3]);
#pragma unroll
        for (int k = 4; k < 32; k += 4) {
            s0 = f2add(s0, c2[k]);       s1 = f2add(s1, c2[k + 1]);
            s2v = f2add(s2v, c2[k + 2]); s3 = f2add(s3, c2[k + 3]);
            q0 = f2fma(c2[k], c2[k], q0);         q1 = f2fma(c2[k + 1], c2[k + 1], q1);
            q2 = f2fma(c2[k + 2], c2[k + 2], q2); q3 = f2fma(c2[k + 3], c2[k + 3], q3);
        }
        u64 ss = f2add(f2add(s0, s1), f2add(s2v, s3));
        u64 qq = f2add(f2add(q0, q1), f2add(q2, q3));
        float a1v, a2v; funp(ss, a1v, a2v); sum = a1v + a2v;
        funp(qq, a1v, a2v); sqs = a1v + a2v;
    }
    const float mean = sum * (1.f / 64.f);
    const float var  = sqs * (1.f / 64.f) - mean * mean;
    const float rstd = rsqrtf(var + 1e-5f);
    {
        u64 nm2 = fdup(-mean), rs2 = fdup(rstd);
        const u64* lgp = (const u64*)g_lngT;
        const u64* lbp = (const u64*)g_lnbT;
        const int col = (p + 8 * g) & 31;      // bank-rotated column for this bt
#pragma unroll
        for (int j = 0; j < 8; j++)
#pragma unroll
            for (int ip = 0; ip < 4; ip++) {
                u64 tv = f2add(c2[j * 4 + ip], nm2);
                tv = f2mul(tv, rs2);
                tv = f2fma(tv, lgp[j * 4 + ip], lbp[j * 4 + ip]);
                float lo, hi; funp(tv, lo, hi);
                // element (i=2ip, j) -> feature e = 16ip + j ; (i=2ip+1) -> e+8
                s_fn[(g * 64 + 16 * ip + j) * 32 + col]     = lo;
                s_fn[(g * 64 + 16 * ip + 8 + j) * 32 + col] = hi;
            }
    }
    __syncthreads();

    // ---- phase 3: f(32x256) @ pw(256x64); thread = 4 bt-rows x 4 cols ----
    {
        const int a = tid >> 4, u = tid & 15;
        u64 acc[4][2];
#pragma unroll
        for (int pi = 0; pi < 4; pi++) { acc[pi][0] = 0ULL; acc[pi][1] = 0ULL; }
#pragma unroll 4
        for (int c = 0; c < 256; c++) {
            const int cb = ((a * 4) + ((c >> 6) * 8)) & 31;
            ulonglong2 fq = *(const ulonglong2*)(s_fn + c * 32 + cb);     // 4 bt vals
            ulonglong2 wv = *(const ulonglong2*)(s_pw + c * 64 + u * 4);  // 4 cols
            float f0, f1, f2v, f3;
            funp(fq.x, f0, f1); funp(fq.y, f2v, f3);
            u64 d0 = fdup(f0), d1 = fdup(f1), dd2 = fdup(f2v), d3 = fdup(f3);
            acc[0][0] = f2fma(d0, wv.x, acc[0][0]);  acc[0][1] = f2fma(d0, wv.y, acc[0][1]);
            acc[1][0] = f2fma(d1, wv.x, acc[1][0]);  acc[1][1] = f2fma(d1, wv.y, acc[1][1]);
            acc[2][0] = f2fma(dd2, wv.x, acc[2][0]); acc[2][1] = f2fma(dd2, wv.y, acc[2][1]);
            acc[3][0] = f2fma(d3, wv.x, acc[3][0]);  acc[3][1] = f2fma(d3, wv.y, acc[3][1]);
        }
        ulonglong2 pbv = *(const ulonglong2*)(pb + u * 4);
        const int base = blockIdx.x * 32 + a * 4;
#pragma unroll
        for (int pi = 0; pi < 4; pi++) {
            ulonglong2 o;
            o.x = f2add(acc[pi][0], pbv.x);
            o.y = f2add(acc[pi][1], pbv.y);
            *(ulonglong2*)(g_fp + (size_t)(base + pi) * 64 + u * 4) = o;
        }
    }
}

// ---------------- K3: masked pooled partials of h = x + interp(f) --------
__global__ void __launch_bounds__(256) k_interp(
    const float* __restrict__ x, const float* __restrict__ mask) {
    const int b  = blockIdx.y;
    const int d  = threadIdx.x & 63;
    const int tq = threadIdx.x >> 6;
    const float scl = (float)(2047.0 / 2048.0);
    float acc = 0.f;
    const int t0 = blockIdx.x * 128;
#pragma unroll 4
    for (int i = 0; i < 32; i++) {
        int t = t0 + i * 4 + tq;
        float pos = ((float)t + 0.5f) * scl - 0.5f;
        pos = fminf(fmaxf(pos, 0.f), 2046.0f);
        float fl = floorf(pos);
        int i0 = (int)fl;
        int i1 = min(i0 + 1, 2046);
        float w = pos - fl;
        float f0 = g_fp[((size_t)b * NTM + i0) * 64 + d];
        float f1 = g_fp[((size_t)b * NTM + i1) * 64 + d];
        size_t xi = ((size_t)b * NT + t) * 64 + d;
        float hv = x[xi] + f0 * (1.f - w) + f1 * w;
        acc += hv * mask[b * NT + t];
    }
    __shared__ float red[256];
    red[threadIdx.x] = acc;
    __syncthreads();
    if (tq == 0) {
        float s = red[d] + red[d + 64] + red[d + 128] + red[d + 192];
        g_part[blockIdx.x * (NB * ND) + b * ND + d] = s;
    }
}

// ---------------- K4: SE gate + mask passthrough ----------
__global__ void k_se(const float* __restrict__ mask,
                     const float* __restrict__ w1, const float* __restrict__ b1,
                     const float* __restrict__ w2, const float* __restrict__ b2,
                     float* __restrict__ outp, long long out_size) {
    const int b = blockIdx.x;
    const int tid = threadIdx.x;
    __shared__ float smv[64];
    __shared__ float hid[4];
    __shared__ float dsh;

    float ds = 0.f;
    for (int t = tid; t < NT; t += 64) ds += mask[b * NT + t];
    smv[tid] = ds;
    __syncthreads();
    if (tid == 0) {
        float s = 0.f;
        for (int i = 0; i < 64; i++) s += smv[i];
        dsh = s;
    }
    __syncthreads();
    const float denom = dsh;

    float pv = 0.f;
#pragma unroll
    for (int c = 0; c < 16; c++) pv += g_part[c * (NB * ND) + b * ND + tid];
    pv /= denom;
    __syncthreads();
    smv[tid] = pv;
    __syncthreads();
    if (tid < 4) {
        float acc = b1[tid];
        for (int dd = 0; dd < 64; dd++) acc += smv[dd] * w1[dd * 4 + tid];
        hid[tid] = 0.5f * acc * (1.f + erff(acc * 0.70710678118654752f)); // exact GELU
    }
    __syncthreads();
    float o = b2[tid];
#pragma unroll
    for (int j = 0; j < 4; j++) o += hid[j] * w2[j * 64 + tid];
    g_sgate[b * ND + tid] = 1.f / (1.f + expf(-o));

    const size_t base = (size_t)NB * NT * ND;
    for (int t = tid; t < NT; t += 64) {
        size_t idx = base + (size_t)b * NT + t;
        if ((long long)idx < out_size) outp[idx] = mask[b * NT + t];
    }
}

// ---------------- K5: out = (x + interp(f)) * s + x  (recompute interp) --
__global__ void __launch_bounds__(256) k_final(
    const float* __restrict__ x, float* __restrict__ out) {
    const int i = blockIdx.x * 256 + threadIdx.x;    // < NB*NT*ND = 2^23
    const int d = i & 63;
    const int t = (i >> 6) & (NT - 1);
    const int b = i >> 17;
    float pos = ((float)t + 0.5f) * (float)(2047.0 / 2048.0) - 0.5f;
    pos = fminf(fmaxf(pos, 0.f), 2046.0f);
    float fl = floorf(pos);
    int i0 = (int)fl;
    int i1 = min(i0 + 1, 2046);
    float w = pos - fl;
    float f0 = g_fp[((size_t)b * NTM + i0) * 64 + d];
    float f1 = g_fp[((size_t)b * NTM + i1) * 64 + d];
    float xv = x[i];
    float hv = xv + f0 * (1.f - w) + f1 * w;
    const float s = g_sgate[b * ND + d];
    out[i] = fmaf(hv, s, xv);
}

// ---------------- launch ---------------------------------------------------
extern "C" void kernel_launch(void* const* d_in, const int* in_sizes, int n_in,
                              void* d_out, int out_size) {
    const float* x    = (const float*)d_in[0];
    const float* mask = (const float*)d_in[1];
    const float* W    = (const float*)d_in[2];
    const float* lng  = (const float*)d_in[3];
    const float* lnb  = (const float*)d_in[4];
    const float* pw   = (const float*)d_in[5];
    const float* pb   = (const float*)d_in[6];
    const float* w1   = (const float*)d_in[7];
    const float* b1   = (const float*)d_in[8];
    const float* w2   = (const float*)d_in[9];
    const float* b2   = (const float*)d_in[10];
    float* out = (float*)d_out;

    const int smem = (16384 + 8192 + 4 * 1032) * 4;   // 114816 bytes
    static int attr_done = 0;
    if (!attr_done) {
        cudaFuncSetAttribute(k_main, cudaFuncAttributeMaxDynamicSharedMemorySize, smem);
        attr_done = 1;
    }

    k_prep<<<17, 256>>>(W, lng, lnb);
    k_main<<<(NB * NTM) / 32, 128, smem>>>(x, mask, pw, pb);   // 4094 blocks
    dim3 gi(16, NB);
    k_interp<<<gi, 256>>>(x, mask);
    k_se<<<NB, 64>>>(mask, w1, b1, w2, b2, out, (long long)out_size);
    k_final<<<(NB * NT * ND) / 256, 256>>>(x, out);            // 32768 blocks
}